// round 6
// baseline (speedup 1.0000x reference)
#include <cuda_runtime.h>
#include <math.h>

#define Bsz  2048
#define Dd   512
#define Cc   128
#define Tt   151
#define ROWS 16
#define G3D  1536
#define THREADS 1024
#define KK   8
#define NTILE 64      // 512 / 8
#define PKK  32
#define PNT  16       // 512 / 32

// ---------------- device scratch ----------------
__device__ float  g_h[Bsz * Dd];
__device__ float  g_G[129 * G3D];       // gi table incl b_ih; row 128 = zero-token
__device__ float  g_WhhT[Dd * G3D];     // [k][3D]
__device__ float2 g_Wproj2[Dd * Cc];    // [k][c] duplicated (w,w)
__device__ int    g_tok[Bsz];

// ---------------- PTX helpers ----------------
__device__ __forceinline__ unsigned smem_u32(const void* p) {
    unsigned a;
    asm("{ .reg .u64 t; cvta.to.shared.u64 t, %1; cvt.u32.u64 %0, t; }" : "=r"(a) : "l"(p));
    return a;
}
__device__ __forceinline__ unsigned long long dup2(float w) {
    unsigned long long r;
    asm("mov.b64 %0, {%1, %1};" : "=l"(r) : "f"(w));
    return r;
}
#define FMA2(c, a, b) asm("fma.rn.f32x2 %0, %1, %2, %0;" : "+l"(c) : "l"(a), "l"(b))
__device__ __forceinline__ void unpk(unsigned long long v, float& lo, float& hi) {
    asm("mov.b64 {%0, %1}, %2;" : "=f"(lo), "=f"(hi) : "l"(v));
}
__device__ __forceinline__ void lds2x64(unsigned long long& a, unsigned long long& b, unsigned addr) {
    asm volatile("ld.shared.v2.b64 {%0, %1}, [%2];" : "=l"(a), "=l"(b) : "r"(addr));
}
__device__ __forceinline__ unsigned long long lds64(unsigned addr) {
    unsigned long long v;
    asm volatile("ld.shared.b64 %0, [%1];" : "=l"(v) : "r"(addr));
    return v;
}
__device__ __forceinline__ float ldsf(unsigned addr) {
    float v; asm volatile("ld.shared.f32 %0, [%1];" : "=f"(v) : "r"(addr)); return v;
}
__device__ __forceinline__ void sts64(unsigned addr, unsigned long long v) {
    asm volatile("st.shared.b64 [%0], %1;" :: "r"(addr), "l"(v));
}
__device__ __forceinline__ void cp16(unsigned dst, const float* src) {
    asm volatile("cp.async.cg.shared.global [%0], [%1], 16;" :: "r"(dst), "l"(src));
}
#define CP_COMMIT() asm volatile("cp.async.commit_group;")
#define CP_WAIT0()  asm volatile("cp.async.wait_group 0;" ::: "memory")
#define CP_WAIT1()  asm volatile("cp.async.wait_group 1;" ::: "memory")

// ---------------- setup ----------------
__global__ void setup_kernel(const float* __restrict__ feat,
                             const float* __restrict__ W_hh,
                             const float* __restrict__ W_proj)
{
    int i = blockIdx.x * blockDim.x + threadIdx.x;
    if (i < Bsz * Dd) g_h[i] = feat[i];
    if (i < Dd * G3D) { int k = i / G3D, j = i - k * G3D; g_WhhT[i] = W_hh[j * Dd + k]; }
    if (i < Dd * Cc)  { int k = i / Cc,  c = i - k * Cc;
                        float w = W_proj[c * Dd + k];
                        g_Wproj2[i] = make_float2(w, w); }
    if (i < Bsz) g_tok[i] = 128;
}

__global__ void gi_table_kernel(const float* __restrict__ embed,
                                const float* __restrict__ W_ih,
                                const float* __restrict__ b_ih)
{
    int i = blockIdx.x * blockDim.x + threadIdx.x;
    if (i >= 129 * G3D) return;
    int c = i / G3D, j = i - c * G3D;
    float s = b_ih[j];
    if (c < Cc) {
        const float* e = embed + c * Dd;
        const float* w = W_ih + j * Dd;
        float acc = 0.f;
        #pragma unroll 4
        for (int k = 0; k < Dd; k++) acc = fmaf(e[k], w[k], acc);
        s += acc;
    }
    g_G[i] = s;
}

// shared layout (bytes):
//   hT  [512*16 f]   @ 0        h transposed hT[k*16+r]; updated in place
//   WT0 [12288 f]    @ 32768    gate W buffer 0 (also reused as P: n-gate partials 512*16f)
//   WT1 [12288 f]    @ 81920    gate W buffer 1
//   PB0 (proj tile)  @ 65536    32KB  (inside old WT region, disjoint from P)
//   PB1 (proj tile)  @ 98304    32KB
//   lg  [16*128 f]   @ 131072
//   tk  [16 i]       @ 139264
#define OFF_WT0  32768u
#define OFF_WT1  81920u
#define OFF_P    32768u
#define OFF_PB0  65536u
#define OFF_PB1  98304u
#define SM_BYTES (139264 + 64)

__global__ void __launch_bounds__(THREADS, 1)
step_kernel(const float* __restrict__ b_hh,
            const float* __restrict__ b_proj,
            float* __restrict__ out,
            int t, int wr_tok)
{
    extern __shared__ float sm[];
    const unsigned base = smem_u32(sm);
    const unsigned HT = base;
    float* lg = sm + 131072 / 4;
    int*   tk = (int*)(sm + 139264 / 4);

    const int tid  = threadIdx.x;
    const bool isA = tid < 512;
    const int j    = tid & 511;          // column 0..511
    const int row0 = blockIdx.x * ROWS;

    // B threads: prefetch gate W tile 0 (12288 floats = 3072 x 16B, 6 per B-thread)
    if (!isA) {
        #pragma unroll
        for (int i = 0; i < 6; i++)
            cp16(base + OFF_WT0 + (j + i * 512) * 16, g_WhhT + (j + i * 512) * 4);
        CP_COMMIT();
    }

    // A threads: load h -> transposed hT[k*16+r] (col j = k, all 16 rows)
    if (isA) {
        float tmp[ROWS];
        #pragma unroll
        for (int r = 0; r < ROWS; r++) tmp[r] = g_h[(row0 + r) * Dd + j];
        float4* d = (float4*)sm;
        #pragma unroll
        for (int q = 0; q < 4; q++)
            d[j * 4 + q] = make_float4(tmp[4*q], tmp[4*q+1], tmp[4*q+2], tmp[4*q+3]);
    }
    if (tid < ROWS) tk[tid] = g_tok[row0 + tid];

    // ---- gate GEMM ----
    // A: gates r,z for col j (16 FMA2/k) ; B: gate n for col j (8 FMA2/k)
    unsigned long long ar[8], az[8];   // A only
    unsigned long long an[8];          // B only
    #pragma unroll
    for (int q = 0; q < 8; q++) { ar[q] = 0ull; az[q] = 0ull; an[q] = 0ull; }

    for (int tl = 0; tl < NTILE; tl++) {
        if (!isA) CP_WAIT0();
        __syncthreads();
        if (!isA && tl + 1 < NTILE) {
            const float* src = g_WhhT + (tl + 1) * KK * G3D;
            unsigned dst = base + ((tl + 1) & 1 ? OFF_WT1 : OFF_WT0);
            #pragma unroll
            for (int i = 0; i < 6; i++)
                cp16(dst + (j + i * 512) * 16, src + (j + i * 512) * 4);
            CP_COMMIT();
        }
        const unsigned wb0 = base + ((tl & 1) ? OFF_WT1 : OFF_WT0) + j * 4;
        const unsigned ha0 = HT + tl * KK * 64;
        if (isA) {
            #pragma unroll
            for (int kk = 0; kk < KK; kk++) {
                unsigned long long h0, h1, h2, h3;
                lds2x64(h0, h1, ha0 + kk * 64);
                lds2x64(h2, h3, ha0 + kk * 64 + 16);
                float wr = ldsf(wb0 + kk * 6144);
                float wz = ldsf(wb0 + kk * 6144 + 2048);
                unsigned long long w2;
                w2 = dup2(wr);
                FMA2(ar[0], h0, w2); FMA2(ar[1], h1, w2);
                FMA2(ar[2], h2, w2); FMA2(ar[3], h3, w2);
                w2 = dup2(wz);
                FMA2(az[0], h0, w2); FMA2(az[1], h1, w2);
                FMA2(az[2], h2, w2); FMA2(az[3], h3, w2);
                lds2x64(h0, h1, ha0 + kk * 64 + 32);
                lds2x64(h2, h3, ha0 + kk * 64 + 48);
                w2 = dup2(wr);
                FMA2(ar[4], h0, w2); FMA2(ar[5], h1, w2);
                FMA2(ar[6], h2, w2); FMA2(ar[7], h3, w2);
                w2 = dup2(wz);
                FMA2(az[4], h0, w2); FMA2(az[5], h1, w2);
                FMA2(az[6], h2, w2); FMA2(az[7], h3, w2);
            }
        } else {
            #pragma unroll
            for (int kk = 0; kk < KK; kk++) {
                unsigned long long h0, h1, h2, h3, h4, h5, h6, h7;
                lds2x64(h0, h1, ha0 + kk * 64);
                lds2x64(h2, h3, ha0 + kk * 64 + 16);
                lds2x64(h4, h5, ha0 + kk * 64 + 32);
                lds2x64(h6, h7, ha0 + kk * 64 + 48);
                float wn = ldsf(wb0 + kk * 6144 + 4096);
                unsigned long long w2 = dup2(wn);
                FMA2(an[0], h0, w2); FMA2(an[1], h1, w2);
                FMA2(an[2], h2, w2); FMA2(an[3], h3, w2);
                FMA2(an[4], h4, w2); FMA2(an[5], h5, w2);
                FMA2(an[6], h6, w2); FMA2(an[7], h7, w2);
            }
        }
    }
    __syncthreads();   // gate GEMM complete; W buffers free

    // B: publish n-gate partials to P, then prefetch proj tiles 0 and 1
    if (!isA) {
        #pragma unroll
        for (int q = 0; q < 8; q++)
            sts64(base + OFF_P + (j * 16 + 2 * q) * 4, an[q]);
        #pragma unroll
        for (int i = 0; i < 4; i++)
            cp16(base + OFF_PB0 + (j + i * 512) * 16, (const float*)g_Wproj2 + (j + i * 512) * 4);
        CP_COMMIT();
        #pragma unroll
        for (int i = 0; i < 4; i++)
            cp16(base + OFF_PB1 + (j + i * 512) * 16, (const float*)(g_Wproj2 + PKK * Cc) + (j + i * 512) * 4);
        CP_COMMIT();
    }
    __syncthreads();   // P visible

    // ---- A: nonlinearity + in-place h update (col j, all 16 rows) ----
    if (isA) {
        const float bhr = b_hh[j], bhz = b_hh[Dd + j], bhn = b_hh[2 * Dd + j];
        float anv[ROWS];
        const float4* Pf4 = (const float4*)(sm + OFF_P / 4);
        #pragma unroll
        for (int q = 0; q < 4; q++) {
            float4 v = Pf4[j * 4 + q];
            anv[4*q] = v.x; anv[4*q+1] = v.y; anv[4*q+2] = v.z; anv[4*q+3] = v.w;
        }
        float hnew[ROWS];
        #pragma unroll
        for (int q = 0; q < 8; q++) {
            float a0, a1, z0, z1;
            unpk(ar[q], a0, a1);
            unpk(az[q], z0, z1);
            #pragma unroll
            for (int s = 0; s < 2; s++) {
                int r = 2 * q + s;
                const float* Gr = g_G + tk[r] * G3D + j;
                float ir = Gr[0], iz = Gr[Dd], in_ = Gr[2 * Dd];
                float av = s ? a1 : a0;
                float zv = s ? z1 : z0;
                float rgate = 1.f / (1.f + expf(-(ir + av + bhr)));
                float zgate = 1.f / (1.f + expf(-(iz + zv + bhz)));
                float ngate = tanhf(in_ + rgate * (anv[r] + bhn));
                float ho    = sm[j * 16 + r];
                hnew[r]     = (1.f - zgate) * ngate + zgate * ho;
            }
        }
        float4* d = (float4*)sm;
        #pragma unroll
        for (int q = 0; q < 4; q++)
            d[j * 4 + q] = make_float4(hnew[4*q], hnew[4*q+1], hnew[4*q+2], hnew[4*q+3]);
        #pragma unroll
        for (int r = 0; r < ROWS; r++)
            g_h[(row0 + r) * Dd + j] = hnew[r];
    }
    __syncthreads();   // h_new visible

    // ---- projection: all 1024 threads; c = tid&127, rows (2pg, 2pg+1) ----
    {
        const int c  = tid & (Cc - 1);
        const int pg = tid >> 7;              // 0..7
        unsigned long long p = 0ull;

        for (int pt = 0; pt < PNT; pt++) {
            if (!isA) CP_WAIT1();
            __syncthreads();
            const unsigned wpb = base + ((pt & 1) ? OFF_PB1 : OFF_PB0) + c * 8;
            const unsigned hb  = HT + (pt * PKK * 16 + 2 * pg) * 4;
            #pragma unroll
            for (int kk = 0; kk < PKK; kk++) {
                unsigned long long w2 = lds64(wpb + kk * 1024);   // (w,w) pair
                unsigned long long h2 = lds64(hb + kk * 64);      // rows 2pg,2pg+1
                FMA2(p, h2, w2);
            }
            __syncthreads();   // everyone done with this buffer
            if (!isA && pt + 2 < PNT) {
                const float* src = (const float*)(g_Wproj2 + (pt + 2) * PKK * Cc);
                unsigned dst = base + ((pt & 1) ? OFF_PB1 : OFF_PB0);
                #pragma unroll
                for (int i = 0; i < 4; i++)
                    cp16(dst + (j + i * 512) * 16, src + (j + i * 512) * 4);
                CP_COMMIT();
            }
        }

        float v0, v1;
        unpk(p, v0, v1);
        const float bp = b_proj[c];
        v0 += bp; v1 += bp;
        int rowA = 2 * pg, rowB = 2 * pg + 1;
        lg[rowA * Cc + c] = v0;
        lg[rowB * Cc + c] = v1;
        out[(size_t)(row0 + rowA) * Cc * Tt + (size_t)c * Tt + t] = v0;
        out[(size_t)(row0 + rowB) * Cc * Tt + (size_t)c * Tt + t] = v1;
    }
    __syncthreads();

    // ---- argmax (first-max tie-break) ----
    if (tid < ROWS) {
        float best = lg[tid * Cc];
        int   bidx = 0;
        #pragma unroll 4
        for (int cq = 1; cq < Cc; cq++) {
            float v = lg[tid * Cc + cq];
            if (v > best) { best = v; bidx = cq; }
        }
        g_tok[row0 + tid] = bidx;
        if (wr_tok)
            out[(size_t)Bsz * Cc * Tt + (size_t)(row0 + tid) * Tt + t] = (float)bidx;
    }
}

// ---------------- launch ----------------
extern "C" void kernel_launch(void* const* d_in, const int* in_sizes, int n_in,
                              void* d_out, int out_size)
{
    const float* feat   = (const float*)d_in[0];
    const float* W_ih   = (const float*)d_in[1];
    const float* W_hh   = (const float*)d_in[2];
    const float* b_ih   = (const float*)d_in[3];
    const float* b_hh   = (const float*)d_in[4];
    const float* W_proj = (const float*)d_in[5];
    const float* b_proj = (const float*)d_in[6];
    const float* embed  = (const float*)d_in[7];
    float* out = (float*)d_out;

    int wr_tok = (out_size >= Bsz * Cc * Tt + Bsz * Tt) ? 1 : 0;

    static int smem_set = 0;
    if (!smem_set) {
        cudaFuncSetAttribute(step_kernel, cudaFuncAttributeMaxDynamicSharedMemorySize, SM_BYTES);
        smem_set = 1;
    }

    setup_kernel<<<(Bsz * Dd + 255) / 256, 256>>>(feat, W_hh, W_proj);
    gi_table_kernel<<<(129 * G3D + 127) / 128, 128>>>(embed, W_ih, b_ih);

    for (int t = 0; t < Tt; t++)
        step_kernel<<<Bsz / ROWS, THREADS, SM_BYTES>>>(b_hh, b_proj, out, t, wr_tok);
}

// round 7
// speedup vs baseline: 1.3117x; 1.3117x over previous
#include <cuda_runtime.h>
#include <math.h>

#define Bsz  2048
#define Dd   512
#define Cc   128
#define Tt   151
#define ROWS 16
#define G3D  1536
#define THREADS 1024
#define KK   8
#define NTILE 64      // 512 / 8
#define PKK  32
#define PNT  16       // 512 / 32

// ---------------- device scratch ----------------
__device__ float g_h[Bsz * Dd];
__device__ float g_G[129 * G3D];        // gi table incl b_ih; row 128 = zero-token
__device__ float g_WhhT[Dd * G3D];      // [k][3D]
__device__ float g_WprojP[Dd * Cc];     // [k][c] plain f32
__device__ int   g_tok[Bsz];

// ---------------- PTX helpers ----------------
__device__ __forceinline__ unsigned smem_u32(const void* p) {
    unsigned a;
    asm("{ .reg .u64 t; cvta.to.shared.u64 t, %1; cvt.u32.u64 %0, t; }" : "=r"(a) : "l"(p));
    return a;
}
__device__ __forceinline__ unsigned long long dup2(float w) {
    unsigned long long r;
    asm("mov.b64 %0, {%1, %1};" : "=l"(r) : "f"(w));
    return r;
}
#define FMA2(c, a, b) asm("fma.rn.f32x2 %0, %1, %2, %0;" : "+l"(c) : "l"(a), "l"(b))
__device__ __forceinline__ void unpk(unsigned long long v, float& lo, float& hi) {
    asm("mov.b64 {%0, %1}, %2;" : "=f"(lo), "=f"(hi) : "l"(v));
}
__device__ __forceinline__ void lds2x64(unsigned long long& a, unsigned long long& b, unsigned addr) {
    asm volatile("ld.shared.v2.b64 {%0, %1}, [%2];" : "=l"(a), "=l"(b) : "r"(addr));
}
__device__ __forceinline__ unsigned long long lds64(unsigned addr) {
    unsigned long long v;
    asm volatile("ld.shared.b64 %0, [%1];" : "=l"(v) : "r"(addr));
    return v;
}
__device__ __forceinline__ float ldsf(unsigned addr) {
    float v; asm volatile("ld.shared.f32 %0, [%1];" : "=f"(v) : "r"(addr)); return v;
}
__device__ __forceinline__ void cp16(unsigned dst, const float* src) {
    asm volatile("cp.async.cg.shared.global [%0], [%1], 16;" :: "r"(dst), "l"(src));
}
#define CP_COMMIT() asm volatile("cp.async.commit_group;")
#define CP_WAIT0()  asm volatile("cp.async.wait_group 0;" ::: "memory")

// ---------------- setup ----------------
__global__ void setup_kernel(const float* __restrict__ feat,
                             const float* __restrict__ W_hh,
                             const float* __restrict__ W_proj)
{
    int i = blockIdx.x * blockDim.x + threadIdx.x;
    if (i < Bsz * Dd) g_h[i] = feat[i];
    if (i < Dd * G3D) { int k = i / G3D, j = i - k * G3D; g_WhhT[i] = W_hh[j * Dd + k]; }
    if (i < Dd * Cc)  { int k = i / Cc,  c = i - k * Cc;  g_WprojP[i] = W_proj[c * Dd + k]; }
    if (i < Bsz) g_tok[i] = 128;
}

__global__ void gi_table_kernel(const float* __restrict__ embed,
                                const float* __restrict__ W_ih,
                                const float* __restrict__ b_ih)
{
    int i = blockIdx.x * blockDim.x + threadIdx.x;
    if (i >= 129 * G3D) return;
    int c = i / G3D, j = i - c * G3D;
    float s = b_ih[j];
    if (c < Cc) {
        const float* e = embed + c * Dd;
        const float* w = W_ih + j * Dd;
        float acc = 0.f;
        #pragma unroll 4
        for (int k = 0; k < Dd; k++) acc = fmaf(e[k], w[k], acc);
        s += acc;
    }
    g_G[i] = s;
}

// shared layout (bytes):
//   hT  [512*16 f] @ 0       h transposed hT[k*16+r]; updated in place
//   WT0 [12288 f]  @ 32768   gate W buffer 0 (48KB)
//   WT1 [12288 f]  @ 81920   gate W buffer 1 (48KB)
//   PB0 [4096  f]  @ 32768   proj tile buffer 0 (16KB, reuses WT0 after gates)
//   PB1 [4096  f]  @ 49152   proj tile buffer 1 (16KB)
//   lg  [16*128 f] @ 131072
//   tk  [16 i]     @ 139264
#define OFF_WT0  32768u
#define OFF_WT1  81920u
#define OFF_PB0  32768u
#define OFF_PB1  49152u
#define SM_BYTES (139264 + 64)

__global__ void __launch_bounds__(THREADS, 1)
step_kernel(const float* __restrict__ b_hh,
            const float* __restrict__ b_proj,
            float* __restrict__ out,
            int t, int wr_tok)
{
    extern __shared__ float sm[];
    const unsigned base = smem_u32(sm);
    const unsigned HT = base;
    float* lg = sm + 131072 / 4;
    int*   tk = (int*)(sm + 139264 / 4);

    const int tid  = threadIdx.x;
    // lane-pairing: the two row-half threads of column j sit in ADJACENT LANES
    // of the same warp -> their duplicate W loads broadcast-merge in the crossbar.
    const int j    = ((tid >> 5) << 4) | ((tid & 31) >> 1);   // column 0..511
    const int rg   = tid & 1;                                 // row half
    const int r0   = rg * 8;
    const int row0 = blockIdx.x * ROWS;

    // prefetch gate W tile 0 (12288 floats = 3072 x 16B, 3 per thread)
    #pragma unroll
    for (int i = 0; i < 3; i++)
        cp16(base + OFF_WT0 + (tid + i * 1024) * 16, g_WhhT + (tid + i * 1024) * 4);
    CP_COMMIT();

    // load h -> transposed hT[k*16+r]; this thread: k=j, rows r0..r0+7
    {
        float tmp[8];
        #pragma unroll
        for (int r = 0; r < 8; r++) tmp[r] = g_h[(row0 + r0 + r) * Dd + j];
        float4* d = (float4*)sm;
        d[j * 4 + rg * 2 + 0] = make_float4(tmp[0], tmp[1], tmp[2], tmp[3]);
        d[j * 4 + rg * 2 + 1] = make_float4(tmp[4], tmp[5], tmp[6], tmp[7]);
    }
    if (tid < ROWS) tk[tid] = g_tok[row0 + tid];

    // ---- gate GEMM: col j, 8 rows packed as 4 f32x2 accumulators per gate ----
    unsigned long long ar[4], az[4], an[4];
    #pragma unroll
    for (int q = 0; q < 4; q++) { ar[q] = 0ull; az[q] = 0ull; an[q] = 0ull; }

    for (int tl = 0; tl < NTILE; tl++) {
        CP_WAIT0();
        __syncthreads();
        if (tl + 1 < NTILE) {
            const float* src = g_WhhT + (tl + 1) * KK * G3D;
            unsigned dst = base + ((tl + 1) & 1 ? OFF_WT1 : OFF_WT0);
            #pragma unroll
            for (int i = 0; i < 3; i++)
                cp16(dst + (tid + i * 1024) * 16, src + (tid + i * 1024) * 4);
            CP_COMMIT();
        }
        const unsigned wb0 = base + ((tl & 1) ? OFF_WT1 : OFF_WT0) + j * 4;
        const unsigned ha0 = HT + tl * KK * 64 + rg * 32;
        #pragma unroll
        for (int kk = 0; kk < KK; kk++) {
            unsigned long long h0, h1, h2, h3;
            lds2x64(h0, h1, ha0 + kk * 64);
            lds2x64(h2, h3, ha0 + kk * 64 + 16);
            float wr = ldsf(wb0 + kk * 6144);
            float wz = ldsf(wb0 + kk * 6144 + 2048);
            float wn = ldsf(wb0 + kk * 6144 + 4096);
            unsigned long long w2;
            w2 = dup2(wr);
            FMA2(ar[0], h0, w2); FMA2(ar[1], h1, w2); FMA2(ar[2], h2, w2); FMA2(ar[3], h3, w2);
            w2 = dup2(wz);
            FMA2(az[0], h0, w2); FMA2(az[1], h1, w2); FMA2(az[2], h2, w2); FMA2(az[3], h3, w2);
            w2 = dup2(wn);
            FMA2(an[0], h0, w2); FMA2(an[1], h1, w2); FMA2(an[2], h2, w2); FMA2(an[3], h3, w2);
        }
    }
    __syncthreads();    // all threads done reading hT and W buffers

    // prefetch proj W tile 0 (32x128 f32 = 16 KB) into PB0 (1 chunk per thread)
    cp16(base + OFF_PB0 + tid * 16, g_WprojP + tid * 4);
    CP_COMMIT();

    // ---- gate nonlinearity + in-place h update (own slots only) ----
    {
        const float bhr = b_hh[j], bhz = b_hh[Dd + j], bhn = b_hh[2 * Dd + j];
        float hnew[8];
        #pragma unroll
        for (int q = 0; q < 4; q++) {
            float a0, a1, z0, z1, n0, n1;
            unpk(ar[q], a0, a1);
            unpk(az[q], z0, z1);
            unpk(an[q], n0, n1);
            #pragma unroll
            for (int s = 0; s < 2; s++) {
                int rl = 2 * q + s;             // 0..7 within this half
                int r  = r0 + rl;               // 0..15 block-local row
                const float* Gr = g_G + tk[r] * G3D + j;
                float ir = Gr[0], iz = Gr[Dd], in_ = Gr[2 * Dd];
                float av = s ? a1 : a0;
                float zv = s ? z1 : z0;
                float nv = s ? n1 : n0;
                float rgate = 1.f / (1.f + expf(-(ir + av + bhr)));
                float zgate = 1.f / (1.f + expf(-(iz + zv + bhz)));
                float ngate = tanhf(in_ + rgate * (nv + bhn));
                float ho    = sm[j * 16 + r];
                hnew[rl]    = (1.f - zgate) * ngate + zgate * ho;
            }
        }
        float4* d = (float4*)sm;
        d[j * 4 + rg * 2 + 0] = make_float4(hnew[0], hnew[1], hnew[2], hnew[3]);
        d[j * 4 + rg * 2 + 1] = make_float4(hnew[4], hnew[5], hnew[6], hnew[7]);
        #pragma unroll
        for (int r = 0; r < 8; r++)
            g_h[(row0 + r0 + r) * Dd + j] = hnew[r];
    }
    __syncthreads();    // h_new visible

    // ---- projection: col c = tid&127, rows (2pg, 2pg+1) packed in one f32x2 ----
    {
        const int c  = tid & (Cc - 1);
        const int pg = tid >> 7;                 // 0..7
        unsigned long long p = 0ull;

        for (int pt = 0; pt < PNT; pt++) {
            CP_WAIT0();
            __syncthreads();
            if (pt + 1 < PNT) {
                const float* src = g_WprojP + (pt + 1) * PKK * Cc;
                unsigned dst = base + (((pt + 1) & 1) ? OFF_PB1 : OFF_PB0);
                cp16(dst + tid * 16, src + tid * 4);
                CP_COMMIT();
            }
            const unsigned wpb = base + ((pt & 1) ? OFF_PB1 : OFF_PB0) + c * 4;
            const unsigned hb  = HT + (pt * PKK * 16 + 2 * pg) * 4;
            #pragma unroll
            for (int kk = 0; kk < PKK; kk++) {
                float wv = ldsf(wpb + kk * 512);
                unsigned long long w2 = dup2(wv);
                unsigned long long h2 = lds64(hb + kk * 64);     // rows 2pg,2pg+1
                FMA2(p, h2, w2);
            }
        }

        float v0, v1;
        unpk(p, v0, v1);
        const float bp = b_proj[c];
        v0 += bp; v1 += bp;
        int rowA = 2 * pg, rowB = 2 * pg + 1;
        lg[rowA * Cc + c] = v0;
        lg[rowB * Cc + c] = v1;
        out[(size_t)(row0 + rowA) * Cc * Tt + (size_t)c * Tt + t] = v0;
        out[(size_t)(row0 + rowB) * Cc * Tt + (size_t)c * Tt + t] = v1;
    }
    __syncthreads();

    // ---- argmax (first-max tie-break) ----
    if (tid < ROWS) {
        float best = lg[tid * Cc];
        int   bidx = 0;
        #pragma unroll 4
        for (int cq = 1; cq < Cc; cq++) {
            float v = lg[tid * Cc + cq];
            if (v > best) { best = v; bidx = cq; }
        }
        g_tok[row0 + tid] = bidx;
        if (wr_tok)
            out[(size_t)Bsz * Cc * Tt + (size_t)(row0 + tid) * Tt + t] = (float)bidx;
    }
}

// ---------------- launch ----------------
extern "C" void kernel_launch(void* const* d_in, const int* in_sizes, int n_in,
                              void* d_out, int out_size)
{
    const float* feat   = (const float*)d_in[0];
    const float* W_ih   = (const float*)d_in[1];
    const float* W_hh   = (const float*)d_in[2];
    const float* b_ih   = (const float*)d_in[3];
    const float* b_hh   = (const float*)d_in[4];
    const float* W_proj = (const float*)d_in[5];
    const float* b_proj = (const float*)d_in[6];
    const float* embed  = (const float*)d_in[7];
    float* out = (float*)d_out;

    int wr_tok = (out_size >= Bsz * Cc * Tt + Bsz * Tt) ? 1 : 0;

    static int smem_set = 0;
    if (!smem_set) {
        cudaFuncSetAttribute(step_kernel, cudaFuncAttributeMaxDynamicSharedMemorySize, SM_BYTES);
        smem_set = 1;
    }

    setup_kernel<<<(Bsz * Dd + 255) / 256, 256>>>(feat, W_hh, W_proj);
    gi_table_kernel<<<(129 * G3D + 127) / 128, 128>>>(embed, W_ih, b_ih);

    for (int t = 0; t < Tt; t++)
        step_kernel<<<Bsz / ROWS, THREADS, SM_BYTES>>>(b_hh, b_proj, out, t, wr_tok);
}

// round 13
// speedup vs baseline: 1.3181x; 1.0049x over previous
#include <cuda_runtime.h>
#include <cuda_bf16.h>
#include <math.h>
#include <stdint.h>

#define Bsz  2048
#define Dd   512
#define Cc   128
#define Tt   151
#define ROWS 16
#define G3D  1536

// K1 GEMM geometry (mma.sync path)
#define TM   128
#define TN   128
#define NMI  16          // 2048/128
#define NNI  12          // 1536/128
#define NCH  8           // 512/64 k64 blocks
#define K1_THREADS 256
#define K1_GRID (NMI*NNI)   // 192
#define NPROD 6
#define NST  (NPROD*NCH)    // 48 stages
#define IMG  16384          // one split image: 128 rows x 64 bf16 (SW128) = 16KB

// K2
#define K2_THREADS 1024
#define PKK  32
#define PNT  16
#define ASPL 16384

#define SWZ128(o) ((o) ^ ((((unsigned)(o))>>3)&0x70))

// ---------------- device scratch ----------------
__device__ float g_h[Bsz * Dd];
__device__ float g_G[129 * G3D];        // gi table incl b_ih; row 128 = zero-token
__device__ float g_GH[(size_t)Bsz * G3D];
__device__ float g_WprojP[Dd * Cc];     // [k][c]
__device__ int   g_tok[Bsz];
// pre-swizzled bf16 split images: [mi|ni][ch][split(3)][128 rows x 64 k]
__device__ __nv_bfloat16 g_Ah[NMI * NCH * 3 * TM * 64];
__device__ __nv_bfloat16 g_Bw[NNI * NCH * 3 * TN * 64];

// ---------------- PTX helpers ----------------
__device__ __forceinline__ unsigned smem_u32(const void* p) {
    unsigned a;
    asm("{ .reg .u64 t; cvta.to.shared.u64 t, %1; cvt.u32.u64 %0, t; }" : "=r"(a) : "l"(p));
    return a;
}
__device__ __forceinline__ unsigned long long dup2(float w) {
    unsigned long long r;
    asm("mov.b64 %0, {%1, %1};" : "=l"(r) : "f"(w));
    return r;
}
#define FMA2(c, a, b) asm("fma.rn.f32x2 %0, %1, %2, %0;" : "+l"(c) : "l"(a), "l"(b))
__device__ __forceinline__ void unpk(unsigned long long v, float& lo, float& hi) {
    asm("mov.b64 {%0, %1}, %2;" : "=f"(lo), "=f"(hi) : "l"(v));
}
__device__ __forceinline__ unsigned long long lds64(unsigned addr) {
    unsigned long long v;
    asm volatile("ld.shared.b64 %0, [%1];" : "=l"(v) : "r"(addr));
    return v;
}
__device__ __forceinline__ float ldsf(unsigned addr) {
    float v; asm volatile("ld.shared.f32 %0, [%1];" : "=f"(v) : "r"(addr)); return v;
}
__device__ __forceinline__ void cp16(unsigned dst, const void* src) {
    asm volatile("cp.async.cg.shared.global [%0], [%1], 16;" :: "r"(dst), "l"(src));
}
#define CP_COMMIT() asm volatile("cp.async.commit_group;")
#define CP_WAIT0()  asm volatile("cp.async.wait_group 0;" ::: "memory")

__device__ __forceinline__ void ldm4(uint32_t& r0, uint32_t& r1, uint32_t& r2, uint32_t& r3,
                                     unsigned addr) {
    asm volatile("ldmatrix.sync.aligned.m8n8.x4.shared.b16 {%0,%1,%2,%3}, [%4];"
                 : "=r"(r0), "=r"(r1), "=r"(r2), "=r"(r3) : "r"(addr));
}
__device__ __forceinline__ void mma16816(float* d, const uint32_t* a, const uint32_t* b) {
    asm volatile(
        "mma.sync.aligned.m16n8k16.row.col.f32.bf16.bf16.f32 "
        "{%0,%1,%2,%3}, {%4,%5,%6,%7}, {%8,%9}, {%0,%1,%2,%3};"
        : "+f"(d[0]), "+f"(d[1]), "+f"(d[2]), "+f"(d[3])
        : "r"(a[0]), "r"(a[1]), "r"(a[2]), "r"(a[3]), "r"(b[0]), "r"(b[1]));
}

__device__ __forceinline__ void split3(float x, __nv_bfloat16& b1, __nv_bfloat16& b2, __nv_bfloat16& b3) {
    b1 = __float2bfloat16(x);
    float r = x - __bfloat162float(b1);
    b2 = __float2bfloat16(r);
    r -= __bfloat162float(b2);
    b3 = __float2bfloat16(r);
}

// ---------------- setup ----------------
__global__ void setup_kernel(const float* __restrict__ feat,
                             const float* __restrict__ W_hh,
                             const float* __restrict__ W_proj)
{
    int i = blockIdx.x * blockDim.x + threadIdx.x;
    if (i < Bsz * Dd) {
        float v = feat[i];
        g_h[i] = v;
        int row = i >> 9, k = i & 511;
        int mi = row >> 7, r = row & 127, ch = k >> 6, kk = k & 63;
        char* bb = (char*)g_Ah + (size_t)(mi * NCH + ch) * 3 * IMG + SWZ128(r * 128 + kk * 2);
        __nv_bfloat16 b1, b2, b3;
        split3(v, b1, b2, b3);
        *(__nv_bfloat16*)(bb)           = b1;
        *(__nv_bfloat16*)(bb + IMG)     = b2;
        *(__nv_bfloat16*)(bb + 2 * IMG) = b3;
    }
    if (i < G3D * Dd) {
        int jj = i >> 9, k = i & 511;
        float v = W_hh[i];
        int ni = jj >> 7, n = jj & 127, ch = k >> 6, kk = k & 63;
        char* bb = (char*)g_Bw + (size_t)(ni * NCH + ch) * 3 * IMG + SWZ128(n * 128 + kk * 2);
        __nv_bfloat16 b1, b2, b3;
        split3(v, b1, b2, b3);
        *(__nv_bfloat16*)(bb)           = b1;
        *(__nv_bfloat16*)(bb + IMG)     = b2;
        *(__nv_bfloat16*)(bb + 2 * IMG) = b3;
    }
    if (i < Dd * Cc) { int k = i / Cc, c = i - k * Cc; g_WprojP[i] = W_proj[c * Dd + k]; }
    if (i < Bsz) g_tok[i] = 128;
}

__global__ void gi_table_kernel(const float* __restrict__ embed,
                                const float* __restrict__ W_ih,
                                const float* __restrict__ b_ih)
{
    int i = blockIdx.x * blockDim.x + threadIdx.x;
    if (i >= 129 * G3D) return;
    int c = i / G3D, j = i - c * G3D;
    float s = b_ih[j];
    if (c < Cc) {
        const float* e = embed + c * Dd;
        const float* w = W_ih + j * Dd;
        float acc = 0.f;
        #pragma unroll 4
        for (int k = 0; k < Dd; k++) acc = fmaf(e[k], w[k], acc);
        s += acc;
    }
    g_G[i] = s;
}

// ---------------- K1: GH = h @ W_hh^T  (mma.sync bf16, 3-split x 6 products) ----------------
// smem: stage buffers [2][A 16KB | B 16KB] = 64KB
#define K1_SMEM (2 * 2 * IMG)

__constant__ int c_PA[NPROD] = {0, 0, 1, 0, 1, 2};
__constant__ int c_PB[NPROD] = {0, 1, 0, 2, 1, 0};

__global__ void __launch_bounds__(K1_THREADS, 1)
gemm_kernel()
{
    extern __shared__ char smc[];
    const unsigned base = smem_u32(smc);
    const int tid  = threadIdx.x;
    const int wid  = tid >> 5;
    const int lane = tid & 31;
    const int mi   = blockIdx.x / NNI;
    const int ni   = blockIdx.x % NNI;
    const int wm   = wid & 1;        // m half (64 rows)
    const int wn   = wid >> 1;       // n quarter (32 cols)

    float acc[64];
    #pragma unroll
    for (int q = 0; q < 64; q++) acc[q] = 0.f;

    const char* Abase = (const char*)g_Ah + (size_t)mi * NCH * 3 * IMG;
    const char* Bbase = (const char*)g_Bw + (size_t)ni * NCH * 3 * IMG;

    // A ldmatrix row/byte per lane (fixed): row = wm*64 + mt*16 + (lane&15), seg = (lane>>4)*16
    const int arow15 = lane & 15;
    const int aseg   = (lane >> 4) * 16;
    // B: row = wn*32 + ntp*16 + (lane&7) + ((lane&16)?8:0), seg = (lane&8)?16:0
    const int brow   = (lane & 7) + ((lane & 16) ? 8 : 0);
    const int bseg   = (lane & 8) ? 16 : 0;

    // prefetch stage 0
    {
        const char* sA = Abase + (size_t)c_PA[0] * IMG;       // ch 0, k6 0
        const char* sB = Bbase + (size_t)c_PB[0] * IMG;
        #pragma unroll
        for (int i = 0; i < 4; i++) cp16(base + (i * 256 + tid) * 16, sA + (i * 256 + tid) * 16);
        #pragma unroll
        for (int i = 0; i < 4; i++) cp16(base + IMG + (i * 256 + tid) * 16, sB + (i * 256 + tid) * 16);
        CP_COMMIT();
    }

    for (int s = 0; s < NST; s++) {
        CP_WAIT0();
        __syncthreads();
        if (s + 1 < NST) {
            int ch = (s + 1) / NCH, k6 = (s + 1) & (NCH - 1);
            const char* sA = Abase + (size_t)(k6 * 3 + c_PA[ch]) * IMG;
            const char* sB = Bbase + (size_t)(k6 * 3 + c_PB[ch]) * IMG;
            unsigned dst = base + ((s + 1) & 1) * 2 * IMG;
            #pragma unroll
            for (int i = 0; i < 4; i++) cp16(dst + (i * 256 + tid) * 16, sA + (i * 256 + tid) * 16);
            #pragma unroll
            for (int i = 0; i < 4; i++) cp16(dst + IMG + (i * 256 + tid) * 16, sB + (i * 256 + tid) * 16);
            CP_COMMIT();
        }
        const unsigned sa = base + (s & 1) * 2 * IMG;
        const unsigned sb = sa + IMG;

        #pragma unroll
        for (int ks = 0; ks < 4; ks++) {
            uint32_t af[4][4];
            #pragma unroll
            for (int mt = 0; mt < 4; mt++) {
                int row = wm * 64 + mt * 16 + arow15;
                unsigned addr = sa + SWZ128((unsigned)(row * 128 + ks * 32 + aseg));
                ldm4(af[mt][0], af[mt][1], af[mt][2], af[mt][3], addr);
            }
            uint32_t bf[4][2];
            #pragma unroll
            for (int ntp = 0; ntp < 2; ntp++) {
                int row = wn * 32 + ntp * 16 + brow;
                unsigned addr = sb + SWZ128((unsigned)(row * 128 + ks * 32 + bseg));
                uint32_t r0, r1, r2, r3;
                ldm4(r0, r1, r2, r3, addr);
                bf[2 * ntp][0] = r0; bf[2 * ntp][1] = r1;
                bf[2 * ntp + 1][0] = r2; bf[2 * ntp + 1][1] = r3;
            }
            #pragma unroll
            for (int mt = 0; mt < 4; mt++)
                #pragma unroll
                for (int nt = 0; nt < 4; nt++)
                    mma16816(&acc[(mt * 4 + nt) * 4], af[mt], bf[nt]);
        }
    }

    // epilogue: write acc -> g_GH  (row-major [2048][1536])
    {
        const int r4 = lane >> 2;      // 0..7
        const int c2 = (lane & 3) * 2; // 0,2,4,6
        #pragma unroll
        for (int mt = 0; mt < 4; mt++) {
            #pragma unroll
            for (int nt = 0; nt < 4; nt++) {
                const float* d = &acc[(mt * 4 + nt) * 4];
                int row0g = mi * 128 + wm * 64 + mt * 16 + r4;
                int colg  = ni * 128 + wn * 32 + nt * 8 + c2;
                *(float2*)(g_GH + (size_t)row0g * G3D + colg)       = make_float2(d[0], d[1]);
                *(float2*)(g_GH + (size_t)(row0g + 8) * G3D + colg) = make_float2(d[2], d[3]);
            }
        }
    }
}

// ---------------- K2: gates + h update + split-store + proj + argmax ----------------
// smem: hT @0 (32KB), PB0 @32768, PB1 @49152, lg @65536 (8KB), tk @73728
#define K2_PB0 32768u
#define K2_PB1 49152u
#define K2_SMEM (73728 + 64)

__global__ void __launch_bounds__(K2_THREADS, 1)
step2_kernel(const float* __restrict__ b_hh,
             const float* __restrict__ b_proj,
             float* __restrict__ out,
             int t, int wr_tok)
{
    extern __shared__ float sm[];
    const unsigned base = smem_u32(sm);
    float* lg = sm + 65536 / 4;
    int*   tk = (int*)(sm + 73728 / 4);

    const int tid  = threadIdx.x;
    const int j    = tid & 511;
    const int rg   = tid >> 9;
    const int r0   = rg * 8;
    const int row0 = blockIdx.x * ROWS;

    // prefetch proj W tile 0 (32x128 f32 = 16KB)
    cp16(base + K2_PB0 + tid * 16, (const char*)g_WprojP + tid * 16);
    CP_COMMIT();

    if (tid < ROWS) tk[tid] = g_tok[row0 + tid];
    __syncthreads();

    // ---- gates + h_new (col j, 8 rows) ----
    {
        const float bhr = b_hh[j], bhz = b_hh[Dd + j], bhn = b_hh[2 * Dd + j];
        const int mi = row0 >> 7, ch = j >> 6, kk = j & 63;
        char* abase = (char*)g_Ah + (size_t)(mi * NCH + ch) * 3 * ASPL;
        #pragma unroll
        for (int rl = 0; rl < 8; rl++) {
            int r = r0 + rl, rowg = row0 + r;
            const float* ghrow = g_GH + (size_t)rowg * G3D;
            float gr = ghrow[j];
            float gz = ghrow[512 + j];
            float gn = ghrow[1024 + j];
            const float* Gr = g_G + tk[r] * G3D + j;
            float ho = g_h[rowg * Dd + j];
            float rgate = 1.f / (1.f + expf(-(Gr[0]   + gr + bhr)));
            float zgate = 1.f / (1.f + expf(-(Gr[512] + gz + bhz)));
            float ngate = tanhf(Gr[1024] + rgate * (gn + bhn));
            float hn = (1.f - zgate) * ngate + zgate * ho;
            g_h[rowg * Dd + j] = hn;
            sm[j * 16 + r]     = hn;            // hT for proj
            int rr = rowg & 127;
            char* bb = abase + SWZ128(rr * 128 + kk * 2);
            __nv_bfloat16 b1, b2, b3;
            split3(hn, b1, b2, b3);
            *(__nv_bfloat16*)(bb)            = b1;
            *(__nv_bfloat16*)(bb + ASPL)     = b2;
            *(__nv_bfloat16*)(bb + 2 * ASPL) = b3;
        }
    }
    __syncthreads();    // hT complete

    // ---- projection: col c = tid&127, rows (2pg, 2pg+1) in one f32x2 ----
    {
        const int c  = tid & (Cc - 1);
        const int pg = tid >> 7;
        unsigned long long p = 0ull;

        for (int pt = 0; pt < PNT; pt++) {
            CP_WAIT0();
            __syncthreads();
            if (pt + 1 < PNT) {
                const float* src = g_WprojP + (pt + 1) * PKK * Cc;
                unsigned dst = base + (((pt + 1) & 1) ? K2_PB1 : K2_PB0);
                cp16(dst + tid * 16, (const char*)src + tid * 16);
                CP_COMMIT();
            }
            const unsigned wpb = base + ((pt & 1) ? K2_PB1 : K2_PB0) + c * 4;
            const unsigned hb  = base + (pt * PKK * 16 + 2 * pg) * 4;
            #pragma unroll
            for (int kq = 0; kq < PKK; kq++) {
                float wv = ldsf(wpb + kq * 512);
                unsigned long long w2 = dup2(wv);
                unsigned long long h2 = lds64(hb + kq * 64);
                FMA2(p, h2, w2);
            }
        }

        float v0, v1;
        unpk(p, v0, v1);
        const float bp = b_proj[c];
        v0 += bp; v1 += bp;
        int rowA = 2 * pg, rowB = 2 * pg + 1;
        lg[rowA * Cc + c] = v0;
        lg[rowB * Cc + c] = v1;
        out[(size_t)(row0 + rowA) * Cc * Tt + (size_t)c * Tt + t] = v0;
        out[(size_t)(row0 + rowB) * Cc * Tt + (size_t)c * Tt + t] = v1;
    }
    __syncthreads();

    // ---- argmax (first-max tie-break) ----
    if (tid < ROWS) {
        float best = lg[tid * Cc];
        int   bidx = 0;
        #pragma unroll 4
        for (int cq = 1; cq < Cc; cq++) {
            float v = lg[tid * Cc + cq];
            if (v > best) { best = v; bidx = cq; }
        }
        g_tok[row0 + tid] = bidx;
        if (wr_tok)
            out[(size_t)Bsz * Cc * Tt + (size_t)(row0 + tid) * Tt + t] = (float)bidx;
    }
}

// ---------------- launch ----------------
extern "C" void kernel_launch(void* const* d_in, const int* in_sizes, int n_in,
                              void* d_out, int out_size)
{
    const float* feat   = (const float*)d_in[0];
    const float* W_ih   = (const float*)d_in[1];
    const float* W_hh   = (const float*)d_in[2];
    const float* b_ih   = (const float*)d_in[3];
    const float* b_hh   = (const float*)d_in[4];
    const float* W_proj = (const float*)d_in[5];
    const float* b_proj = (const float*)d_in[6];
    const float* embed  = (const float*)d_in[7];
    float* out = (float*)d_out;

    int wr_tok = (out_size >= Bsz * Cc * Tt + Bsz * Tt) ? 1 : 0;

    cudaFuncSetAttribute(gemm_kernel,  cudaFuncAttributeMaxDynamicSharedMemorySize, K1_SMEM);
    cudaFuncSetAttribute(step2_kernel, cudaFuncAttributeMaxDynamicSharedMemorySize, K2_SMEM);

    setup_kernel<<<(Bsz * Dd + 255) / 256, 256>>>(feat, W_hh, W_proj);
    gi_table_kernel<<<(129 * G3D + 127) / 128, 128>>>(embed, W_ih, b_ih);

    for (int t = 0; t < Tt; t++) {
        gemm_kernel<<<K1_GRID, K1_THREADS, K1_SMEM>>>();
        step2_kernel<<<Bsz / ROWS, K2_THREADS, K2_SMEM>>>(b_hh, b_proj, out, t, wr_tok);
    }
}

// round 14
// speedup vs baseline: 1.7042x; 1.2930x over previous
#include <cuda_runtime.h>
#include <cuda_bf16.h>
#include <math.h>
#include <stdint.h>

#define Bsz  2048
#define Dd   512
#define Cc   128
#define Tt   151
#define ROWS 16
#define G3D  1536

// K1 GEMM geometry (mma.sync path)
#define TM   128
#define TN   192
#define NMI  16          // 2048/128
#define NNI  8           // 1536/192
#define NCH  8           // 512/64 k64 blocks
#define K1_THREADS 256
#define K1_GRID (NMI*NNI)   // 128 -> single wave
#define NST  48             // 6 products x 8 chunks
#define IMG   16384         // A split image: 128 x 64 bf16 (SW128)
#define BIMG  24576         // B split image: 192 x 64 bf16 (SW128)

// K2
#define K2_THREADS 1024

#define SWZ128(o) ((o) ^ ((((unsigned)(o))>>3)&0x70))

// ---------------- device scratch ----------------
__device__ float g_h[Bsz * Dd];
__device__ float g_G[129 * G3D];        // gi table incl b_ih; row 128 = zero-token
__device__ float g_GH[(size_t)Bsz * G3D];
__device__ float g_WprojP[Dd * Cc];     // [k][c]
__device__ int   g_tok[Bsz];
// pre-swizzled bf16 split images: [tile][ch][split(3)][rows x 64 k]
__device__ __nv_bfloat16 g_Ah[NMI * NCH * 3 * TM * 64];
__device__ __nv_bfloat16 g_Bw[NNI * NCH * 3 * TN * 64];

// ---------------- PTX helpers ----------------
__device__ __forceinline__ unsigned smem_u32(const void* p) {
    unsigned a;
    asm("{ .reg .u64 t; cvta.to.shared.u64 t, %1; cvt.u32.u64 %0, t; }" : "=r"(a) : "l"(p));
    return a;
}
__device__ __forceinline__ unsigned long long dup2(float w) {
    unsigned long long r;
    asm("mov.b64 %0, {%1, %1};" : "=l"(r) : "f"(w));
    return r;
}
#define FMA2(c, a, b) asm("fma.rn.f32x2 %0, %1, %2, %0;" : "+l"(c) : "l"(a), "l"(b))
__device__ __forceinline__ void unpk(unsigned long long v, float& lo, float& hi) {
    asm("mov.b64 {%0, %1}, %2;" : "=f"(lo), "=f"(hi) : "l"(v));
}
__device__ __forceinline__ unsigned long long lds64(unsigned addr) {
    unsigned long long v;
    asm volatile("ld.shared.b64 %0, [%1];" : "=l"(v) : "r"(addr));
    return v;
}
__device__ __forceinline__ void cp16(unsigned dst, const void* src) {
    asm volatile("cp.async.cg.shared.global [%0], [%1], 16;" :: "r"(dst), "l"(src));
}
#define CP_COMMIT() asm volatile("cp.async.commit_group;")
#define CP_WAIT0()  asm volatile("cp.async.wait_group 0;" ::: "memory")

__device__ __forceinline__ void ldm4(uint32_t& r0, uint32_t& r1, uint32_t& r2, uint32_t& r3,
                                     unsigned addr) {
    asm volatile("ldmatrix.sync.aligned.m8n8.x4.shared.b16 {%0,%1,%2,%3}, [%4];"
                 : "=r"(r0), "=r"(r1), "=r"(r2), "=r"(r3) : "r"(addr));
}
__device__ __forceinline__ void mma16816(float* d, const uint32_t* a, const uint32_t* b) {
    asm volatile(
        "mma.sync.aligned.m16n8k16.row.col.f32.bf16.bf16.f32 "
        "{%0,%1,%2,%3}, {%4,%5,%6,%7}, {%8,%9}, {%0,%1,%2,%3};"
        : "+f"(d[0]), "+f"(d[1]), "+f"(d[2]), "+f"(d[3])
        : "r"(a[0]), "r"(a[1]), "r"(a[2]), "r"(a[3]), "r"(b[0]), "r"(b[1]));
}

__device__ __forceinline__ void split3(float x, __nv_bfloat16& b1, __nv_bfloat16& b2, __nv_bfloat16& b3) {
    b1 = __float2bfloat16(x);
    float r = x - __bfloat162float(b1);
    b2 = __float2bfloat16(r);
    r -= __bfloat162float(b2);
    b3 = __float2bfloat16(r);
}

// ---------------- setup ----------------
__global__ void setup_kernel(const float* __restrict__ feat,
                             const float* __restrict__ W_hh,
                             const float* __restrict__ W_proj)
{
    int i = blockIdx.x * blockDim.x + threadIdx.x;
    if (i < Bsz * Dd) {
        float v = feat[i];
        g_h[i] = v;
        int row = i >> 9, k = i & 511;
        int mi = row >> 7, r = row & 127, ch = k >> 6, kk = k & 63;
        char* bb = (char*)g_Ah + (size_t)(mi * NCH + ch) * 3 * IMG + SWZ128(r * 128 + kk * 2);
        __nv_bfloat16 b1, b2, b3;
        split3(v, b1, b2, b3);
        *(__nv_bfloat16*)(bb)           = b1;
        *(__nv_bfloat16*)(bb + IMG)     = b2;
        *(__nv_bfloat16*)(bb + 2 * IMG) = b3;
    }
    if (i < G3D * Dd) {
        int jj = i >> 9, k = i & 511;
        float v = W_hh[i];
        int ni = jj / TN, n = jj % TN, ch = k >> 6, kk = k & 63;
        char* bb = (char*)g_Bw + (size_t)(ni * NCH + ch) * 3 * BIMG + SWZ128(n * 128 + kk * 2);
        __nv_bfloat16 b1, b2, b3;
        split3(v, b1, b2, b3);
        *(__nv_bfloat16*)(bb)            = b1;
        *(__nv_bfloat16*)(bb + BIMG)     = b2;
        *(__nv_bfloat16*)(bb + 2 * BIMG) = b3;
    }
    if (i < Dd * Cc) { int k = i / Cc, c = i - k * Cc; g_WprojP[i] = W_proj[c * Dd + k]; }
    if (i < Bsz) g_tok[i] = 128;
}

__global__ void gi_table_kernel(const float* __restrict__ embed,
                                const float* __restrict__ W_ih,
                                const float* __restrict__ b_ih)
{
    int i = blockIdx.x * blockDim.x + threadIdx.x;
    if (i >= 129 * G3D) return;
    int c = i / G3D, j = i - c * G3D;
    float s = b_ih[j];
    if (c < Cc) {
        const float* e = embed + c * Dd;
        const float* w = W_ih + j * Dd;
        float acc = 0.f;
        #pragma unroll 4
        for (int k = 0; k < Dd; k++) acc = fmaf(e[k], w[k], acc);
        s += acc;
    }
    g_G[i] = s;
}

// ---------------- K1: GH = h @ W_hh^T (mma.sync bf16, 3-split x 6 products) ----------------
// Per-chunk product order (pa,pb): (0,2),(0,1),(0,0),(1,0),(1,1),(2,0)
// A loads at ps {0,3,5}; B loads at ps {0,1,2}; 3 loads each per chunk ->
// load-counter parity p = ch&1 selects buffers; all reuse hazards barrier-separated.
__constant__ int c_pa[6] = {0,0,0,1,1,2};
__constant__ int c_pb[6] = {2,1,0,0,1,0};
__constant__ int c_ac[6] = {0,0,0,1,1,0};   // A consume buf ^ p
__constant__ int c_bc[6] = {0,1,0,0,1,0};   // B consume buf ^ p
__constant__ int c_al[6] = {1,0,0,1,0,1};   // A load happens at this ps
__constant__ int c_bl[6] = {1,1,1,0,0,0};   // B load happens at this ps

// smem: A0 @0, A1 @16384, B0 @32768, B1 @57344
#define K1_SMEM 81920

__global__ void __launch_bounds__(K1_THREADS, 1)
gemm_kernel()
{
    extern __shared__ char smc[];
    const unsigned base = smem_u32(smc);
    const int tid  = threadIdx.x;
    const int wid  = tid >> 5;
    const int lane = tid & 31;
    const int mi   = blockIdx.x >> 3;
    const int ni   = blockIdx.x & 7;
    const int wm   = wid & 1;        // m half (64 rows)
    const int wn   = wid >> 1;       // n slice (48 cols)

    float acc[96];
    #pragma unroll
    for (int q = 0; q < 96; q++) acc[q] = 0.f;

    const char* Abase = (const char*)g_Ah + (size_t)mi * NCH * 3 * IMG;
    const char* Bbase = (const char*)g_Bw + (size_t)ni * NCH * 3 * BIMG;

    const int arow15 = lane & 15;
    const int aseg   = (lane >> 4) * 16;
    const int brow   = (lane & 7) + ((lane & 16) ? 8 : 0);
    const int bseg   = (lane & 8) ? 16 : 0;

    // prologue: loads for stage 0 (ch0, ps0: A img 0 -> A0, B img 2 -> B0)
    {
        const char* sA = Abase + (size_t)c_pa[0] * IMG;
        const char* sB = Bbase + (size_t)c_pb[0] * BIMG;
        #pragma unroll
        for (int i = 0; i < 4; i++) cp16(base + (i * 256 + tid) * 16, sA + (i * 256 + tid) * 16);
        #pragma unroll
        for (int i = 0; i < 6; i++) cp16(base + 32768u + (i * 256 + tid) * 16, sB + (i * 256 + tid) * 16);
        CP_COMMIT();
    }

    for (int s = 0; s < NST; s++) {
        CP_WAIT0();
        __syncthreads();

        // prefetch for stage s+1
        if (s + 1 < NST) {
            const int t1 = s + 1, ch1 = t1 / 6, ps1 = t1 % 6, p1 = ch1 & 1;
            if (c_al[ps1]) {
                const char* sA = Abase + (size_t)(ch1 * 3 + c_pa[ps1]) * IMG;
                unsigned dst = base + (unsigned)(c_ac[ps1] ^ p1) * 16384u;
                #pragma unroll
                for (int i = 0; i < 4; i++) cp16(dst + (i * 256 + tid) * 16, sA + (i * 256 + tid) * 16);
            }
            if (c_bl[ps1]) {
                const char* sB = Bbase + (size_t)(ch1 * 3 + c_pb[ps1]) * BIMG;
                unsigned dst = base + 32768u + (unsigned)(c_bc[ps1] ^ p1) * 24576u;
                #pragma unroll
                for (int i = 0; i < 6; i++) cp16(dst + (i * 256 + tid) * 16, sB + (i * 256 + tid) * 16);
            }
            CP_COMMIT();
        }

        const int ch = s / 6, ps = s % 6, p = ch & 1;
        const unsigned sa = base + (unsigned)(c_ac[ps] ^ p) * 16384u;
        const unsigned sb = base + 32768u + (unsigned)(c_bc[ps] ^ p) * 24576u;

        #pragma unroll
        for (int ks = 0; ks < 4; ks++) {
            uint32_t af[4][4];
            #pragma unroll
            for (int mt = 0; mt < 4; mt++) {
                int row = wm * 64 + mt * 16 + arow15;
                unsigned addr = sa + SWZ128((unsigned)(row * 128 + ks * 32 + aseg));
                ldm4(af[mt][0], af[mt][1], af[mt][2], af[mt][3], addr);
            }
            uint32_t bf[6][2];
            #pragma unroll
            for (int ntp = 0; ntp < 3; ntp++) {
                int row = wn * 48 + ntp * 16 + brow;
                unsigned addr = sb + SWZ128((unsigned)(row * 128 + ks * 32 + bseg));
                uint32_t r0, r1, r2, r3;
                ldm4(r0, r1, r2, r3, addr);
                bf[2 * ntp][0] = r0;     bf[2 * ntp][1] = r1;
                bf[2 * ntp + 1][0] = r2; bf[2 * ntp + 1][1] = r3;
            }
            #pragma unroll
            for (int mt = 0; mt < 4; mt++)
                #pragma unroll
                for (int nt = 0; nt < 6; nt++)
                    mma16816(&acc[(mt * 6 + nt) * 4], af[mt], bf[nt]);
        }
    }

    // epilogue: acc -> g_GH (row-major [2048][1536])
    {
        const int r4 = lane >> 2;
        const int c2 = (lane & 3) * 2;
        #pragma unroll
        for (int mt = 0; mt < 4; mt++) {
            #pragma unroll
            for (int nt = 0; nt < 6; nt++) {
                const float* d = &acc[(mt * 6 + nt) * 4];
                int rowg = mi * 128 + wm * 64 + mt * 16 + r4;
                int colg = ni * 192 + wn * 48 + nt * 8 + c2;
                *(float2*)(g_GH + (size_t)rowg * G3D + colg)       = make_float2(d[0], d[1]);
                *(float2*)(g_GH + (size_t)(rowg + 8) * G3D + colg) = make_float2(d[2], d[3]);
            }
        }
    }
}

// ---------------- K2: gates + h update + split-store + proj + argmax ----------------
// smem: hT @0 (32KB), lg @32768 (8KB), tk @40960
#define K2_SMEM (40960 + 64)

__global__ void __launch_bounds__(K2_THREADS, 1)
step2_kernel(const float* __restrict__ b_hh,
             const float* __restrict__ b_proj,
             float* __restrict__ out,
             int t, int wr_tok)
{
    extern __shared__ float sm[];
    const unsigned base = smem_u32(sm);
    float* lg = sm + 32768 / 4;
    int*   tk = (int*)(sm + 40960 / 4);

    const int tid  = threadIdx.x;
    const int j    = tid & 511;
    const int rg   = tid >> 9;
    const int r0   = rg * 8;
    const int row0 = blockIdx.x * ROWS;

    if (tid < ROWS) tk[tid] = g_tok[row0 + tid];
    __syncthreads();

    // ---- gates + h_new (col j, 8 rows) ----
    {
        const float bhr = b_hh[j], bhz = b_hh[Dd + j], bhn = b_hh[2 * Dd + j];
        const int mi = row0 >> 7, ch = j >> 6, kk = j & 63;
        char* abase = (char*)g_Ah + (size_t)(mi * NCH + ch) * 3 * IMG;
        #pragma unroll
        for (int rl = 0; rl < 8; rl++) {
            int r = r0 + rl, rowg = row0 + r;
            const float* ghrow = g_GH + (size_t)rowg * G3D;
            float gr = ghrow[j];
            float gz = ghrow[512 + j];
            float gn = ghrow[1024 + j];
            const float* Gr = g_G + tk[r] * G3D + j;
            float ho = g_h[rowg * Dd + j];
            float rgate = 1.f / (1.f + expf(-(Gr[0]   + gr + bhr)));
            float zgate = 1.f / (1.f + expf(-(Gr[512] + gz + bhz)));
            float ngate = tanhf(Gr[1024] + rgate * (gn + bhn));
            float hn = (1.f - zgate) * ngate + zgate * ho;
            g_h[rowg * Dd + j] = hn;
            sm[j * 16 + r]     = hn;            // hT for proj
            int rr = rowg & 127;
            char* bb = abase + SWZ128(rr * 128 + kk * 2);
            __nv_bfloat16 b1, b2, b3;
            split3(hn, b1, b2, b3);
            *(__nv_bfloat16*)(bb)           = b1;
            *(__nv_bfloat16*)(bb + IMG)     = b2;
            *(__nv_bfloat16*)(bb + 2 * IMG) = b3;
        }
    }
    __syncthreads();    // hT complete

    // ---- projection: col c = tid&127, rows (2pg, 2pg+1); W from L2 directly ----
    {
        const int c  = tid & (Cc - 1);
        const int pg = tid >> 7;
        unsigned long long p = 0ull;
        const float* wp = g_WprojP + c;
        const unsigned hb = base + (2 * pg) * 4;

        #pragma unroll 8
        for (int k = 0; k < Dd; k++) {
            float wv = __ldg(wp + k * Cc);
            unsigned long long w2 = dup2(wv);
            unsigned long long h2 = lds64(hb + k * 64);
            FMA2(p, h2, w2);
        }

        float v0, v1;
        unpk(p, v0, v1);
        const float bp = b_proj[c];
        v0 += bp; v1 += bp;
        int rowA = 2 * pg, rowB = 2 * pg + 1;
        lg[rowA * Cc + c] = v0;
        lg[rowB * Cc + c] = v1;
        out[(size_t)(row0 + rowA) * Cc * Tt + (size_t)c * Tt + t] = v0;
        out[(size_t)(row0 + rowB) * Cc * Tt + (size_t)c * Tt + t] = v1;
    }
    __syncthreads();

    // ---- argmax (first-max tie-break) ----
    if (tid < ROWS) {
        float best = lg[tid * Cc];
        int   bidx = 0;
        #pragma unroll 4
        for (int cq = 1; cq < Cc; cq++) {
            float v = lg[tid * Cc + cq];
            if (v > best) { best = v; bidx = cq; }
        }
        g_tok[row0 + tid] = bidx;
        if (wr_tok)
            out[(size_t)Bsz * Cc * Tt + (size_t)(row0 + tid) * Tt + t] = (float)bidx;
    }
}

// ---------------- launch ----------------
extern "C" void kernel_launch(void* const* d_in, const int* in_sizes, int n_in,
                              void* d_out, int out_size)
{
    const float* feat   = (const float*)d_in[0];
    const float* W_ih   = (const float*)d_in[1];
    const float* W_hh   = (const float*)d_in[2];
    const float* b_ih   = (const float*)d_in[3];
    const float* b_hh   = (const float*)d_in[4];
    const float* W_proj = (const float*)d_in[5];
    const float* b_proj = (const float*)d_in[6];
    const float* embed  = (const float*)d_in[7];
    float* out = (float*)d_out;

    int wr_tok = (out_size >= Bsz * Cc * Tt + Bsz * Tt) ? 1 : 0;

    cudaFuncSetAttribute(gemm_kernel,  cudaFuncAttributeMaxDynamicSharedMemorySize, K1_SMEM);
    cudaFuncSetAttribute(step2_kernel, cudaFuncAttributeMaxDynamicSharedMemorySize, K2_SMEM);

    setup_kernel<<<(Bsz * Dd + 255) / 256, 256>>>(feat, W_hh, W_proj);
    gi_table_kernel<<<(129 * G3D + 127) / 128, 128>>>(embed, W_ih, b_ih);

    for (int t = 0; t < Tt; t++) {
        gemm_kernel<<<K1_GRID, K1_THREADS, K1_SMEM>>>();
        step2_kernel<<<Bsz / ROWS, K2_THREADS, K2_SMEM>>>(b_hh, b_proj, out, t, wr_tok);
    }
}

// round 15
// speedup vs baseline: 1.7364x; 1.0189x over previous
#include <cuda_runtime.h>
#include <cuda_bf16.h>
#include <math.h>
#include <stdint.h>

#define Bsz  2048
#define Dd   512
#define Cc   128
#define Tt   151
#define ROWS 16
#define G3D  1536

// K1 GEMM geometry (mma.sync path)
#define TM   128
#define TN   192
#define NMI  16          // 2048/128
#define NNI  8           // 1536/192
#define NCH  8           // 512/64 k64 blocks
#define K1_THREADS 256
#define K1_GRID (NMI*NNI)   // 128 -> single wave
#define NST  48             // 6 products x 8 chunks
#define IMG   16384         // A split image: 128 x 64 bf16 (SW128)
#define BIMG  24576         // B split image: 192 x 64 bf16 (SW128)

// K2
#define K2_THREADS 1024
#define PKK  64
#define PNT  8              // 512/64 proj k-tiles

#define SWZ128(o) ((o) ^ ((((unsigned)(o))>>3)&0x70))

// ---------------- device scratch ----------------
__device__ float g_h[Bsz * Dd];
__device__ float g_G[129 * G3D];        // gi table incl b_ih; row 128 = zero-token
__device__ float g_GH[(size_t)Bsz * G3D];
__device__ float g_WprojP[Dd * Cc];     // [k][c]
__device__ int   g_tok[Bsz];
// pre-swizzled bf16 split images: [tile][ch][split(3)][rows x 64 k]
__device__ __nv_bfloat16 g_Ah[NMI * NCH * 3 * TM * 64];
__device__ __nv_bfloat16 g_Bw[NNI * NCH * 3 * TN * 64];

// ---------------- PTX helpers ----------------
__device__ __forceinline__ unsigned smem_u32(const void* p) {
    unsigned a;
    asm("{ .reg .u64 t; cvta.to.shared.u64 t, %1; cvt.u32.u64 %0, t; }" : "=r"(a) : "l"(p));
    return a;
}
__device__ __forceinline__ unsigned long long dup2(float w) {
    unsigned long long r;
    asm("mov.b64 %0, {%1, %1};" : "=l"(r) : "f"(w));
    return r;
}
#define FMA2(c, a, b) asm("fma.rn.f32x2 %0, %1, %2, %0;" : "+l"(c) : "l"(a), "l"(b))
__device__ __forceinline__ void unpk(unsigned long long v, float& lo, float& hi) {
    asm("mov.b64 {%0, %1}, %2;" : "=f"(lo), "=f"(hi) : "l"(v));
}
__device__ __forceinline__ unsigned long long lds64(unsigned addr) {
    unsigned long long v;
    asm volatile("ld.shared.b64 %0, [%1];" : "=l"(v) : "r"(addr));
    return v;
}
__device__ __forceinline__ float ldsf(unsigned addr) {
    float v; asm volatile("ld.shared.f32 %0, [%1];" : "=f"(v) : "r"(addr)); return v;
}
__device__ __forceinline__ void cp16(unsigned dst, const void* src) {
    asm volatile("cp.async.cg.shared.global [%0], [%1], 16;" :: "r"(dst), "l"(src));
}
#define CP_COMMIT() asm volatile("cp.async.commit_group;")
#define CP_WAIT0()  asm volatile("cp.async.wait_group 0;" ::: "memory")

__device__ __forceinline__ void ldm4(uint32_t& r0, uint32_t& r1, uint32_t& r2, uint32_t& r3,
                                     unsigned addr) {
    asm volatile("ldmatrix.sync.aligned.m8n8.x4.shared.b16 {%0,%1,%2,%3}, [%4];"
                 : "=r"(r0), "=r"(r1), "=r"(r2), "=r"(r3) : "r"(addr));
}
__device__ __forceinline__ void mma16816(float* d, const uint32_t* a, const uint32_t* b) {
    asm volatile(
        "mma.sync.aligned.m16n8k16.row.col.f32.bf16.bf16.f32 "
        "{%0,%1,%2,%3}, {%4,%5,%6,%7}, {%8,%9}, {%0,%1,%2,%3};"
        : "+f"(d[0]), "+f"(d[1]), "+f"(d[2]), "+f"(d[3])
        : "r"(a[0]), "r"(a[1]), "r"(a[2]), "r"(a[3]), "r"(b[0]), "r"(b[1]));
}

__device__ __forceinline__ void split3(float x, __nv_bfloat16& b1, __nv_bfloat16& b2, __nv_bfloat16& b3) {
    b1 = __float2bfloat16(x);
    float r = x - __bfloat162float(b1);
    b2 = __float2bfloat16(r);
    r -= __bfloat162float(b2);
    b3 = __float2bfloat16(r);
}

// ---------------- setup ----------------
__global__ void setup_kernel(const float* __restrict__ feat,
                             const float* __restrict__ W_hh,
                             const float* __restrict__ W_proj)
{
    int i = blockIdx.x * blockDim.x + threadIdx.x;
    if (i < Bsz * Dd) {
        float v = feat[i];
        g_h[i] = v;
        int row = i >> 9, k = i & 511;
        int mi = row >> 7, r = row & 127, ch = k >> 6, kk = k & 63;
        char* bb = (char*)g_Ah + (size_t)(mi * NCH + ch) * 3 * IMG + SWZ128(r * 128 + kk * 2);
        __nv_bfloat16 b1, b2, b3;
        split3(v, b1, b2, b3);
        *(__nv_bfloat16*)(bb)           = b1;
        *(__nv_bfloat16*)(bb + IMG)     = b2;
        *(__nv_bfloat16*)(bb + 2 * IMG) = b3;
    }
    if (i < G3D * Dd) {
        int jj = i >> 9, k = i & 511;
        float v = W_hh[i];
        int ni = jj / TN, n = jj % TN, ch = k >> 6, kk = k & 63;
        char* bb = (char*)g_Bw + (size_t)(ni * NCH + ch) * 3 * BIMG + SWZ128(n * 128 + kk * 2);
        __nv_bfloat16 b1, b2, b3;
        split3(v, b1, b2, b3);
        *(__nv_bfloat16*)(bb)            = b1;
        *(__nv_bfloat16*)(bb + BIMG)     = b2;
        *(__nv_bfloat16*)(bb + 2 * BIMG) = b3;
    }
    if (i < Dd * Cc) { int k = i / Cc, c = i - k * Cc; g_WprojP[i] = W_proj[c * Dd + k]; }
    if (i < Bsz) g_tok[i] = 128;
}

__global__ void gi_table_kernel(const float* __restrict__ embed,
                                const float* __restrict__ W_ih,
                                const float* __restrict__ b_ih)
{
    int i = blockIdx.x * blockDim.x + threadIdx.x;
    if (i >= 129 * G3D) return;
    int c = i / G3D, j = i - c * G3D;
    float s = b_ih[j];
    if (c < Cc) {
        const float* e = embed + c * Dd;
        const float* w = W_ih + j * Dd;
        float acc = 0.f;
        #pragma unroll 4
        for (int k = 0; k < Dd; k++) acc = fmaf(e[k], w[k], acc);
        s += acc;
    }
    g_G[i] = s;
}

// ---------------- K1: GH = h @ W_hh^T (mma.sync bf16, 3-split x 6 products) ----------------
__constant__ int c_pa[6] = {0,0,0,1,1,2};
__constant__ int c_pb[6] = {2,1,0,0,1,0};
__constant__ int c_ac[6] = {0,0,0,1,1,0};   // A consume buf ^ p
__constant__ int c_bc[6] = {0,1,0,0,1,0};   // B consume buf ^ p
__constant__ int c_al[6] = {1,0,0,1,0,1};   // A load happens at this ps
__constant__ int c_bl[6] = {1,1,1,0,0,0};   // B load happens at this ps

// smem: A0 @0, A1 @16384, B0 @32768, B1 @57344
#define K1_SMEM 81920

__global__ void __launch_bounds__(K1_THREADS, 1)
gemm_kernel()
{
    extern __shared__ char smc[];
    const unsigned base = smem_u32(smc);
    const int tid  = threadIdx.x;
    const int wid  = tid >> 5;
    const int lane = tid & 31;
    const int mi   = blockIdx.x >> 3;
    const int ni   = blockIdx.x & 7;
    const int wm   = wid & 1;        // m half (64 rows)
    const int wn   = wid >> 1;       // n slice (48 cols)

    float acc[96];
    #pragma unroll
    for (int q = 0; q < 96; q++) acc[q] = 0.f;

    const char* Abase = (const char*)g_Ah + (size_t)mi * NCH * 3 * IMG;
    const char* Bbase = (const char*)g_Bw + (size_t)ni * NCH * 3 * BIMG;

    const int arow15 = lane & 15;
    const int aseg   = (lane >> 4) * 16;
    const int brow   = (lane & 7) + ((lane & 16) ? 8 : 0);
    const int bseg   = (lane & 8) ? 16 : 0;

    // prologue: loads for stage 0
    {
        const char* sA = Abase + (size_t)c_pa[0] * IMG;
        const char* sB = Bbase + (size_t)c_pb[0] * BIMG;
        #pragma unroll
        for (int i = 0; i < 4; i++) cp16(base + (i * 256 + tid) * 16, sA + (i * 256 + tid) * 16);
        #pragma unroll
        for (int i = 0; i < 6; i++) cp16(base + 32768u + (i * 256 + tid) * 16, sB + (i * 256 + tid) * 16);
        CP_COMMIT();
    }

    for (int s = 0; s < NST; s++) {
        CP_WAIT0();
        __syncthreads();

        if (s + 1 < NST) {
            const int t1 = s + 1, ch1 = t1 / 6, ps1 = t1 % 6, p1 = ch1 & 1;
            if (c_al[ps1]) {
                const char* sA = Abase + (size_t)(ch1 * 3 + c_pa[ps1]) * IMG;
                unsigned dst = base + (unsigned)(c_ac[ps1] ^ p1) * 16384u;
                #pragma unroll
                for (int i = 0; i < 4; i++) cp16(dst + (i * 256 + tid) * 16, sA + (i * 256 + tid) * 16);
            }
            if (c_bl[ps1]) {
                const char* sB = Bbase + (size_t)(ch1 * 3 + c_pb[ps1]) * BIMG;
                unsigned dst = base + 32768u + (unsigned)(c_bc[ps1] ^ p1) * 24576u;
                #pragma unroll
                for (int i = 0; i < 6; i++) cp16(dst + (i * 256 + tid) * 16, sB + (i * 256 + tid) * 16);
            }
            CP_COMMIT();
        }

        const int ch = s / 6, ps = s % 6, p = ch & 1;
        const unsigned sa = base + (unsigned)(c_ac[ps] ^ p) * 16384u;
        const unsigned sb = base + 32768u + (unsigned)(c_bc[ps] ^ p) * 24576u;

        #pragma unroll
        for (int ks = 0; ks < 4; ks++) {
            uint32_t af[4][4];
            #pragma unroll
            for (int mt = 0; mt < 4; mt++) {
                int row = wm * 64 + mt * 16 + arow15;
                unsigned addr = sa + SWZ128((unsigned)(row * 128 + ks * 32 + aseg));
                ldm4(af[mt][0], af[mt][1], af[mt][2], af[mt][3], addr);
            }
            uint32_t bf[6][2];
            #pragma unroll
            for (int ntp = 0; ntp < 3; ntp++) {
                int row = wn * 48 + ntp * 16 + brow;
                unsigned addr = sb + SWZ128((unsigned)(row * 128 + ks * 32 + bseg));
                uint32_t r0, r1, r2, r3;
                ldm4(r0, r1, r2, r3, addr);
                bf[2 * ntp][0] = r0;     bf[2 * ntp][1] = r1;
                bf[2 * ntp + 1][0] = r2; bf[2 * ntp + 1][1] = r3;
            }
            #pragma unroll
            for (int mt = 0; mt < 4; mt++)
                #pragma unroll
                for (int nt = 0; nt < 6; nt++)
                    mma16816(&acc[(mt * 6 + nt) * 4], af[mt], bf[nt]);
        }
    }

    // epilogue: acc -> g_GH (row-major [2048][1536])
    {
        const int r4 = lane >> 2;
        const int c2 = (lane & 3) * 2;
        #pragma unroll
        for (int mt = 0; mt < 4; mt++) {
            #pragma unroll
            for (int nt = 0; nt < 6; nt++) {
                const float* d = &acc[(mt * 6 + nt) * 4];
                int rowg = mi * 128 + wm * 64 + mt * 16 + r4;
                int colg = ni * 192 + wn * 48 + nt * 8 + c2;
                *(float2*)(g_GH + (size_t)rowg * G3D + colg)       = make_float2(d[0], d[1]);
                *(float2*)(g_GH + (size_t)(rowg + 8) * G3D + colg) = make_float2(d[2], d[3]);
            }
        }
    }
}

// ---------------- K2: gates + h update + split-store + proj + argmax ----------------
// smem: hT @0 (32KB), PB0 @32768 (32KB), PB1 @65536 (32KB), lg @98304 (8KB), tk @106496
#define K2_PB0 32768u
#define K2_PB1 65536u
#define K2_SMEM (106496 + 64)

__global__ void __launch_bounds__(K2_THREADS, 1)
step2_kernel(const float* __restrict__ b_hh,
             const float* __restrict__ b_proj,
             float* __restrict__ out,
             int t, int wr_tok)
{
    extern __shared__ float sm[];
    const unsigned base = smem_u32(sm);
    float* lg = sm + 98304 / 4;
    int*   tk = (int*)(sm + 106496 / 4);

    const int tid  = threadIdx.x;
    const int j    = tid & 511;
    const int rg   = tid >> 9;
    const int r0   = rg * 8;
    const int row0 = blockIdx.x * ROWS;

    // prefetch proj W tile 0 (64x128 f32 = 32KB) -> lands during the gate phase
    #pragma unroll
    for (int i = 0; i < 2; i++)
        cp16(base + K2_PB0 + (i * 1024 + tid) * 16, (const char*)g_WprojP + (i * 1024 + tid) * 16);
    CP_COMMIT();

    if (tid < ROWS) tk[tid] = g_tok[row0 + tid];
    __syncthreads();

    // ---- gates + h_new (col j, 8 rows) ----
    {
        const float bhr = b_hh[j], bhz = b_hh[Dd + j], bhn = b_hh[2 * Dd + j];
        const int mi = row0 >> 7, ch = j >> 6, kk = j & 63;
        char* abase = (char*)g_Ah + (size_t)(mi * NCH + ch) * 3 * IMG;
        #pragma unroll
        for (int rl = 0; rl < 8; rl++) {
            int r = r0 + rl, rowg = row0 + r;
            const float* ghrow = g_GH + (size_t)rowg * G3D;
            float gr = ghrow[j];
            float gz = ghrow[512 + j];
            float gn = ghrow[1024 + j];
            const float* Gr = g_G + tk[r] * G3D + j;
            float ho = g_h[rowg * Dd + j];
            float rgate = 1.f / (1.f + expf(-(Gr[0]   + gr + bhr)));
            float zgate = 1.f / (1.f + expf(-(Gr[512] + gz + bhz)));
            float ngate = tanhf(Gr[1024] + rgate * (gn + bhn));
            float hn = (1.f - zgate) * ngate + zgate * ho;
            g_h[rowg * Dd + j] = hn;
            sm[j * 16 + r]     = hn;            // hT for proj
            int rr = rowg & 127;
            char* bb = abase + SWZ128(rr * 128 + kk * 2);
            __nv_bfloat16 b1, b2, b3;
            split3(hn, b1, b2, b3);
            *(__nv_bfloat16*)(bb)           = b1;
            *(__nv_bfloat16*)(bb + IMG)     = b2;
            *(__nv_bfloat16*)(bb + 2 * IMG) = b3;
        }
    }
    __syncthreads();    // hT complete

    // ---- projection: col c = tid&127, rows (2pg, 2pg+1); smem-pipelined W ----
    {
        const int c  = tid & (Cc - 1);
        const int pg = tid >> 7;
        unsigned long long p = 0ull;

        for (int pt = 0; pt < PNT; pt++) {
            CP_WAIT0();
            __syncthreads();
            if (pt + 1 < PNT) {
                const char* src = (const char*)(g_WprojP + (pt + 1) * PKK * Cc);
                unsigned dst = base + (((pt + 1) & 1) ? K2_PB1 : K2_PB0);
                #pragma unroll
                for (int i = 0; i < 2; i++)
                    cp16(dst + (i * 1024 + tid) * 16, src + (i * 1024 + tid) * 16);
                CP_COMMIT();
            }
            const unsigned wpb = base + ((pt & 1) ? K2_PB1 : K2_PB0) + c * 4;
            const unsigned hb  = base + (pt * PKK * 16 + 2 * pg) * 4;
            #pragma unroll
            for (int kq = 0; kq < PKK; kq++) {
                float wv = ldsf(wpb + kq * 512);
                unsigned long long w2 = dup2(wv);
                unsigned long long h2 = lds64(hb + kq * 64);
                FMA2(p, h2, w2);
            }
        }

        float v0, v1;
        unpk(p, v0, v1);
        const float bp = b_proj[c];
        v0 += bp; v1 += bp;
        int rowA = 2 * pg, rowB = 2 * pg + 1;
        lg[rowA * Cc + c] = v0;
        lg[rowB * Cc + c] = v1;
        out[(size_t)(row0 + rowA) * Cc * Tt + (size_t)c * Tt + t] = v0;
        out[(size_t)(row0 + rowB) * Cc * Tt + (size_t)c * Tt + t] = v1;
    }
    __syncthreads();

    // ---- argmax (first-max tie-break) ----
    if (tid < ROWS) {
        float best = lg[tid * Cc];
        int   bidx = 0;
        #pragma unroll 4
        for (int cq = 1; cq < Cc; cq++) {
            float v = lg[tid * Cc + cq];
            if (v > best) { best = v; bidx = cq; }
        }
        g_tok[row0 + tid] = bidx;
        if (wr_tok)
            out[(size_t)Bsz * Cc * Tt + (size_t)(row0 + tid) * Tt + t] = (float)bidx;
    }
}

// ---------------- launch ----------------
extern "C" void kernel_launch(void* const* d_in, const int* in_sizes, int n_in,
                              void* d_out, int out_size)
{
    const float* feat   = (const float*)d_in[0];
    const float* W_ih   = (const float*)d_in[1];
    const float* W_hh   = (const float*)d_in[2];
    const float* b_ih   = (const float*)d_in[3];
    const float* b_hh   = (const float*)d_in[4];
    const float* W_proj = (const float*)d_in[5];
    const float* b_proj = (const float*)d_in[6];
    const float* embed  = (const float*)d_in[7];
    float* out = (float*)d_out;

    int wr_tok = (out_size >= Bsz * Cc * Tt + Bsz * Tt) ? 1 : 0;

    cudaFuncSetAttribute(gemm_kernel,  cudaFuncAttributeMaxDynamicSharedMemorySize, K1_SMEM);
    cudaFuncSetAttribute(step2_kernel, cudaFuncAttributeMaxDynamicSharedMemorySize, K2_SMEM);

    setup_kernel<<<(Bsz * Dd + 255) / 256, 256>>>(feat, W_hh, W_proj);
    gi_table_kernel<<<(129 * G3D + 127) / 128, 128>>>(embed, W_ih, b_ih);

    for (int t = 0; t < Tt; t++) {
        gemm_kernel<<<K1_GRID, K1_THREADS, K1_SMEM>>>();
        step2_kernel<<<Bsz / ROWS, K2_THREADS, K2_SMEM>>>(b_hh, b_proj, out, t, wr_tok);
    }
}